// round 17
// baseline (speedup 1.0000x reference)
#include <cuda_runtime.h>
#include <cuda_bf16.h>
#include <cuda_fp16.h>

// Problem constants (fixed by dataset)
#define N_TIME   64
#define N_BATCH  8192
#define N_STATE  32
#define N_FORCE  16
#define DT_STEP  0.05f

#define WARPS_PER_BLOCK 4
#define THREADS_PER_BLOCK (WARPS_PER_BLOCK * 32)

typedef unsigned long long u64;

// Precomputed fu = U u_t + b for t = 1..63, layout [t-1][elt][state] (float).
#define FU_STEPS (N_TIME - 1)
__device__ float g_fu[(size_t)FU_STEPS * N_BATCH * N_STATE];

__device__ __forceinline__ u64 fma2(u64 a, u64 b, u64 c) {
    u64 d;
    asm("fma.rn.f32x2 %0, %1, %2, %3;" : "=l"(d) : "l"(a), "l"(b), "l"(c));
    return d;
}
__device__ __forceinline__ u64 add2(u64 a, u64 b) {
    u64 d;
    asm("add.rn.f32x2 %0, %1, %2;" : "=l"(d) : "l"(a), "l"(b));
    return d;
}
__device__ __forceinline__ u64 pk2(float x, float y) {
    u64 r;
    asm("mov.b64 %0, {%1, %2};" : "=l"(r) : "f"(x), "f"(y));
    return r;
}
__device__ __forceinline__ void upk2(u64 v, float& x, float& y) {
    asm("mov.b64 {%0, %1}, %2;" : "=f"(x), "=f"(y) : "l"(v));
}

// HW tanh (MUFU, ~5e-4 abs): predictor + middle iteration only.
__device__ __forceinline__ float tanh_approx(float x) {
    float r;
    asm("tanh.approx.f32 %0, %1;" : "=f"(r) : "f"(x));
    return r;
}
// Accurate tanh (~1e-7): final iteration (sets the trajectory error floor).
__device__ __forceinline__ float tanh_exact(float x) {
    x = fminf(fmaxf(x, -9.0f), 9.0f);
    float e = __expf(2.0f * x);
    return __fdividef(e - 1.0f, e + 1.0f);
}

// Dot of this lane's FULL W row (16 f32x2 regs = 32 coeffs) with y stored as
// 32 HALVES in smem (64 B): 4 broadcast LDS.128 (halved L1 wavefronts vs fp32),
// half2 -> float2 convert, packed fma2 accumulate.
__device__ __forceinline__ float matvec_row_h(const __half* __restrict__ buf,
                                              const u64* __restrict__ wl)
{
    const uint4* yv = (const uint4*)buf;
    u64 a = 0ULL, b = 0ULL;
#pragma unroll
    for (int i = 0; i < 4; i++) {                 // 4 x 16B = 64B = 32 halves
        uint4 q = yv[i];
        float2 f0 = __half22float2(*reinterpret_cast<__half2*>(&q.x));
        float2 f1 = __half22float2(*reinterpret_cast<__half2*>(&q.y));
        float2 f2 = __half22float2(*reinterpret_cast<__half2*>(&q.z));
        float2 f3 = __half22float2(*reinterpret_cast<__half2*>(&q.w));
        a = fma2(wl[4 * i + 0], pk2(f0.x, f0.y), a);
        b = fma2(wl[4 * i + 1], pk2(f1.x, f1.y), b);
        a = fma2(wl[4 * i + 2], pk2(f2.x, f2.y), a);
        b = fma2(wl[4 * i + 3], pk2(f3.x, f3.y), b);
    }
    u64 s = add2(a, b);
    float lo, hi;
    upk2(s, lo, hi);
    return lo + hi;
}

// ── Fused kernel: fu prologue + 63 sequential implicit steps with predictor
// + 2 Picard matvecs. Lane l owns W row l; warp owns 2 elements. Iterates are
// exchanged through fp16 smem (64 B per vector -> half the L1 wavefronts).
// __launch_bounds__(128,7): 7 CTAs/SM -> single wave at grid 1024. ──
__global__ __launch_bounds__(THREADS_PER_BLOCK, 7)
void recsolve_kernel(const float* __restrict__ y0,
                     const float* __restrict__ forces,
                     const float* __restrict__ Wmat,
                     const float* __restrict__ Umat,
                     const float* __restrict__ bvec,
                     float* __restrict__ out)
{
    // Per warp: 4 fp16 buffers of 32 halves (elemA/elemB x double-buffer).
    __shared__ __align__(16) __half ysh[WARPS_PER_BLOCK][4][N_STATE];

    const int wib  = threadIdx.x >> 5;
    const int lane = threadIdx.x & 31;
    const int elt0 = (blockIdx.x * WARPS_PER_BLOCK + wib) * 2;
    const int elt1 = elt0 + 1;

    const float bl = bvec[lane];

    // ── Prologue: fu[t][elt][lane] = b[lane] + U_row_lane . u_t for own 2 elems. ──
    {
        u64 ul[N_FORCE / 2];
        const ulonglong2* Up = (const ulonglong2*)(Umat + (size_t)lane * N_FORCE);
#pragma unroll
        for (int j = 0; j < 4; j++) { ulonglong2 q = Up[j]; ul[2*j] = q.x; ul[2*j+1] = q.y; }

        float* fuout = g_fu + (size_t)elt0 * N_STATE + lane;
#pragma unroll 2
        for (int t = 1; t < N_TIME; t++) {
#pragma unroll
            for (int e = 0; e < 2; e++) {
                const ulonglong2* fp =
                    (const ulonglong2*)(forces + ((size_t)t * N_BATCH + elt0 + e) * N_FORCE);
                ulonglong2 q0 = fp[0], q1 = fp[1], q2 = fp[2], q3 = fp[3];
                u64 a = pk2(bl, 0.0f);
                a = fma2(ul[0], q0.x, a);
                a = fma2(ul[1], q0.y, a);
                a = fma2(ul[2], q1.x, a);
                a = fma2(ul[3], q1.y, a);
                a = fma2(ul[4], q2.x, a);
                a = fma2(ul[5], q2.y, a);
                a = fma2(ul[6], q3.x, a);
                a = fma2(ul[7], q3.y, a);
                float lo, hi;
                upk2(a, lo, hi);
                fuout[(size_t)(t - 1) * (N_BATCH * N_STATE) + e * N_STATE] = lo + hi;
            }
        }
    }

    // ── W row for this lane, packed along K as f32x2 pairs (16 u64 regs). ──
    u64 wl[N_STATE / 2];
    {
        const ulonglong2* Wp = (const ulonglong2*)(Wmat + (size_t)lane * N_STATE);
#pragma unroll
        for (int j = 0; j < 8; j++) { ulonglong2 q = Wp[j]; wl[2*j] = q.x; wl[2*j+1] = q.y; }
    }

    __half* bufA0 = ysh[wib][0];
    __half* bufB0 = ysh[wib][1];
    __half* bufA1 = ysh[wib][2];
    __half* bufB1 = ysh[wib][3];

    float yA = y0[(size_t)elt0 * N_STATE + lane];
    float yB = y0[(size_t)elt1 * N_STATE + lane];
    out[(size_t)elt0 * N_STATE + lane] = yA;     // out[0] = y0
    out[(size_t)elt1 * N_STATE + lane] = yB;

    // Carried z = W * y0 (fp16-quantized y0 — error is contracted by the solve).
    bufA0[lane] = __float2half_rn(yA);
    bufB0[lane] = __float2half_rn(yB);
    __syncwarp();
    float zA = matvec_row_h(bufA0, wl);
    float zB = matvec_row_h(bufB0, wl);
    __syncwarp();   // all lanes done reading buf*0 before t=1 overwrites

    const float* fuP = g_fu + (size_t)elt0 * N_STATE + lane;  // slot (t-1)=0
    const size_t fustride = (size_t)N_BATCH * N_STATE;
    float fuA = fuP[0];
    float fuB = fuP[N_STATE];

    for (int t = 1; t < N_TIME; t++) {
        // One-step-ahead prefetch of fu (L2-resident; clamped at the end).
        const int tn = (t < N_TIME - 1) ? t : t - 1;
        float fuA_n = fuP[(size_t)tn * fustride];
        float fuB_n = fuP[(size_t)tn * fustride + N_STATE];

        // Free predictor from carried z = W*y_prev: Picard iterate 0.
        float ygA = fmaf(DT_STEP, tanh_approx(zA + fuA), yA);
        float ygB = fmaf(DT_STEP, tanh_approx(zB + fuB), yB);

        // Iteration 1 (fp16 exchange + approx tanh). Quantization of y_g is
        // contracted by c^2 -> negligible.
        bufA0[lane] = __float2half_rn(ygA);
        bufB0[lane] = __float2half_rn(ygB);
        __syncwarp();
        float gA = matvec_row_h(bufA0, wl);
        float gB = matvec_row_h(bufB0, wl);
        float y1A = fmaf(DT_STEP, tanh_approx(gA + fuA), yA);
        float y1B = fmaf(DT_STEP, tanh_approx(gB + fuB), yB);

        // Iteration 2 (fp16 exchange + exact tanh); matvec result carried as z.
        bufA1[lane] = __float2half_rn(y1A);
        bufB1[lane] = __float2half_rn(y1B);
        __syncwarp();
        zA = matvec_row_h(bufA1, wl);
        zB = matvec_row_h(bufB1, wl);
        yA = fmaf(DT_STEP, tanh_exact(zA + fuA), yA);
        yB = fmaf(DT_STEP, tanh_exact(zB + fuB), yB);

        out[((size_t)t * N_BATCH + elt0) * N_STATE + lane] = yA;
        out[((size_t)t * N_BATCH + elt1) * N_STATE + lane] = yB;
        fuA = fuA_n;
        fuB = fuB_n;
    }
}

extern "C" void kernel_launch(void* const* d_in, const int* in_sizes, int n_in,
                              void* d_out, int out_size)
{
    const float* y0     = (const float*)d_in[0];
    const float* forces = (const float*)d_in[1];
    const float* W      = (const float*)d_in[2];
    const float* U      = (const float*)d_in[3];
    const float* b      = (const float*)d_in[4];
    float* out = (float*)d_out;

    // 1024 blocks x 4 warps x 2 elems = 8192 elements; single wave at 7 CTAs/SM.
    dim3 grid(N_BATCH / (WARPS_PER_BLOCK * 2));
    recsolve_kernel<<<grid, THREADS_PER_BLOCK>>>(y0, forces, W, U, b, out);
}